// round 6
// baseline (speedup 1.0000x reference)
#include <cuda_runtime.h>
#include <math.h>

#define NPTS   2048
#define NGAB   2
#define IMG_H  512
#define IMG_W  512
#define HW     (IMG_H * IMG_W)
#define RENDER_SZ (3 * HW)
#define ALPHA_THRESH (1.0f / 255.0f)

#define NBLOCKS  296            // 2 blocks per SM (148 SMs)
#define NTHREADS 512
#define TOT_THREADS (NBLOCKS * NTHREADS)   // 151552

// Persistent accumulator: zero at module load; phase 2 re-zeroes touched
// entries after consuming, so every replay sees zeros.
__device__ float g_accum[RENDER_SZ];
// Monotonic barrier counter (never reset; generation = count / NBLOCKS).
__device__ unsigned g_bar;

__device__ __forceinline__ float sigmoidf_(float v) {
    return 1.0f / (1.0f + __expf(-v));
}

// Replay-safe grid barrier. All NBLOCKS are co-resident (2/SM guaranteed by
// __launch_bounds__(512,2), 40 regs, 0 smem), so spinning cannot deadlock.
__device__ __forceinline__ void grid_barrier() {
    __syncthreads();
    if (threadIdx.x == 0) {
        __threadfence();                       // release prior atomics/stores
        unsigned arrival = atomicAdd(&g_bar, 1u);
        unsigned target = (arrival / NBLOCKS + 1u) * NBLOCKS;
        volatile unsigned* vb = &g_bar;
        while (*vb < target) { }
    }
    __syncthreads();
    __threadfence();                           // acquire
}

__global__ void __launch_bounds__(NTHREADS, 2)
fused_kernel(const float* __restrict__ xyz,
             const float* __restrict__ cov2d,
             const float* __restrict__ fdc,
             const float* __restrict__ opac,
             const float* __restrict__ gfreq,
             const float* __restrict__ gwt,
             float* __restrict__ out, int out_size) {
    int lane = threadIdx.x & 31;
    int wg   = blockIdx.x * (NTHREADS / 32) + (threadIdx.x >> 5);  // 0..4735

    // ------------- Phase 1: scatter splat, exactly one warp per Gaussian ----
    if (wg < NPTS) {
        int g = wg;
        float sxx = cov2d[3 * g + 0] + 0.5f;
        float sxy = cov2d[3 * g + 1];
        float syy = cov2d[3 * g + 2] + 0.5f;
        float det = sxx * syy - sxy * sxy;
        bool valid = det > 1e-8f;
        float det_s = valid ? det : 1.0f;
        float ca =  syy / det_s;
        float cb = -sxy / det_s;
        float cc =  sxx / det_s;

        float mid = 0.5f * (sxx + syy);
        float lam = mid + sqrtf(fmaxf(mid * mid - det, 0.1f));
        int radii = valid ? (int)ceilf(3.0f * sqrtf(lam)) : 0;

        if (lane == 0) {
            if (out_size >= RENDER_SZ + NPTS)
                out[RENDER_SZ + g] = (float)radii;
            if (out_size >= RENDER_SZ + 2 * NPTS)
                out[RENDER_SZ + NPTS + g] = (radii > 0) ? 1.0f : 0.0f;
        }

        float x  = xyz[2 * g + 0];
        float y  = xyz[2 * g + 1];
        float op = opac[g];

        // Support cutoff: alpha >= 1/255  <=>  sigma <= Tcut.
        float Tcut = __logf(fmaxf(op, 1e-30f) * 255.0f);
        if (valid && Tcut > 0.0f) {
            float cr  = sigmoidf_(fdc[3 * g + 0]);
            float cg  = sigmoidf_(fdc[3 * g + 1]);
            float cbl = sigmoidf_(fdc[3 * g + 2]);
            float fx0 = __expf(gfreq[(g * NGAB + 0) * 2 + 0]);
            float fy0 = __expf(gfreq[(g * NGAB + 0) * 2 + 1]);
            float fx1 = __expf(gfreq[(g * NGAB + 1) * 2 + 0]);
            float fy1 = __expf(gfreq[(g * NGAB + 1) * 2 + 1]);
            float w0  = sigmoidf_(gwt[g * NGAB + 0]);
            float w1  = sigmoidf_(gwt[g * NGAB + 1]);

            // Conservative bbox (superset of {alpha >= 1/255}) + 1px slop.
            float dxm = sqrtf(2.0f * Tcut * sxx) + 1.0f;
            float dym = sqrtf(2.0f * Tcut * syy) + 1.0f;
            int x0 = max(0, (int)floorf(x - dxm - 0.5f));
            int x1 = min(IMG_W - 1, (int)ceilf(x + dxm - 0.5f));
            int y0 = max(0, (int)floorf(y - dym - 0.5f));
            int y1 = min(IMG_H - 1, (int)ceilf(y + dym - 0.5f));
            int bw = x1 - x0 + 1;
            int bh = y1 - y0 + 1;
            if (bw > 0 && bh > 0) {
                int npix = bw * bh;
                for (int t = lane; t < npix; t += 32) {
                    int px = x0 + (t % bw);
                    int py = y0 + (t / bw);
                    float dx = ((float)px + 0.5f) - x;
                    float dy = ((float)py + 0.5f) - y;
                    float sigma = 0.5f * (ca * dx * dx + cc * dy * dy) + cb * (dx * dy);
                    float alpha = fminf(op * __expf(-sigma), 0.999f);
                    if (alpha < ALPHA_THRESH) continue;   // exact reference threshold
                    float arg0 = fx0 * dx + fy0 * dy;
                    float arg1 = fx1 * dx + fy1 * dy;
                    float mod = 1.0f + w0 * __cosf(arg0) + w1 * __cosf(arg1);
                    float wgt = alpha * mod;
                    int pix = py * IMG_W + px;
                    atomicAdd(&g_accum[pix],          wgt * cr);
                    atomicAdd(&g_accum[HW + pix],     wgt * cg);
                    atomicAdd(&g_accum[2 * HW + pix], wgt * cbl);
                }
            }
        }
    }

    // ------------- barrier: all atomics done & visible ----------------------
    grid_barrier();

    // ------------- Phase 2: clamp-sweep accum -> out, re-zero accum ---------
    // 196608 float4s over 151552 threads: <=2 per thread, both loads up front.
    float4* acc4 = reinterpret_cast<float4*>(g_accum);
    float4* out4 = reinterpret_cast<float4*>(out);
    const int n4 = RENDER_SZ / 4;
    int i0 = blockIdx.x * NTHREADS + threadIdx.x;
    int i1 = i0 + TOT_THREADS;
    bool has1 = (i1 < n4);

    float4 a = acc4[i0];
    float4 b = has1 ? acc4[i1] : make_float4(0.f, 0.f, 0.f, 0.f);

    float4 ra;
    ra.x = fminf(fmaxf(a.x, 0.0f), 1.0f);
    ra.y = fminf(fmaxf(a.y, 0.0f), 1.0f);
    ra.z = fminf(fmaxf(a.z, 0.0f), 1.0f);
    ra.w = fminf(fmaxf(a.w, 0.0f), 1.0f);
    out4[i0] = ra;
    if ((a.x != 0.f) | (a.y != 0.f) | (a.z != 0.f) | (a.w != 0.f))
        acc4[i0] = make_float4(0.f, 0.f, 0.f, 0.f);

    if (has1) {
        float4 rb;
        rb.x = fminf(fmaxf(b.x, 0.0f), 1.0f);
        rb.y = fminf(fmaxf(b.y, 0.0f), 1.0f);
        rb.z = fminf(fmaxf(b.z, 0.0f), 1.0f);
        rb.w = fminf(fmaxf(b.w, 0.0f), 1.0f);
        out4[i1] = rb;
        if ((b.x != 0.f) | (b.y != 0.f) | (b.z != 0.f) | (b.w != 0.f))
            acc4[i1] = make_float4(0.f, 0.f, 0.f, 0.f);
    }
}

extern "C" void kernel_launch(void* const* d_in, const int* in_sizes, int n_in,
                              void* d_out, int out_size) {
    const float* xyz   = (const float*)d_in[0];
    const float* cov2d = (const float*)d_in[1];
    const float* fdc   = (const float*)d_in[2];
    const float* opac  = (const float*)d_in[3];
    const float* gfreq = (const float*)d_in[4];
    const float* gwt   = (const float*)d_in[5];
    float* out = (float*)d_out;

    fused_kernel<<<NBLOCKS, NTHREADS>>>(xyz, cov2d, fdc, opac, gfreq, gwt, out, out_size);
}

// round 7
// speedup vs baseline: 1.0061x; 1.0061x over previous
#include <cuda_runtime.h>
#include <math.h>

#define NPTS   2048
#define NGAB   2
#define IMG_H  512
#define IMG_W  512
#define HW     (IMG_H * IMG_W)
#define RENDER_SZ (3 * HW)
#define ALPHA_THRESH (1.0f / 255.0f)

// Interleaved accumulator: one float4 (R,G,B,unused) per pixel. Zero at module
// load; finish re-zeroes touched pixels, so every replay sees zeros.
__device__ float4 g_accum[HW];

__device__ __forceinline__ float sigmoidf_(float v) {
    return 1.0f / (1.0f + __expf(-v));
}

// Vector reduction: one REDG covering all 3 channels (sm_90+ red.add.v4.f32).
__device__ __forceinline__ void red_add_v4(float4* addr, float r, float g, float b) {
    asm volatile("red.global.add.v4.f32 [%0], {%1, %2, %3, %4};"
                 :: "l"(addr), "f"(r), "f"(g), "f"(b), "f"(0.0f)
                 : "memory");
}

// One warp per Gaussian: prep from broadcast (vectorized) loads, then splat
// the conservative bbox with the exact reference alpha threshold per pixel.
__global__ void __launch_bounds__(256)
splat_kernel(const float* __restrict__ xyz,
             const float* __restrict__ cov2d,
             const float* __restrict__ fdc,
             const float* __restrict__ opac,
             const float* __restrict__ gfreq,
             const float* __restrict__ gwt,
             float* __restrict__ out, int out_size) {
    int g    = (blockIdx.x * blockDim.x + threadIdx.x) >> 5;
    int lane = threadIdx.x & 31;
    if (g >= NPTS) return;

    // Vectorized broadcast loads (shorter serial load chain in prep).
    float2 xy = reinterpret_cast<const float2*>(xyz)[g];
    float4 gf = reinterpret_cast<const float4*>(gfreq)[g];   // (i,2,2) = 4 contiguous
    float2 gw = reinterpret_cast<const float2*>(gwt)[g];

    float sxx = cov2d[3 * g + 0] + 0.5f;
    float sxy = cov2d[3 * g + 1];
    float syy = cov2d[3 * g + 2] + 0.5f;
    float det = sxx * syy - sxy * sxy;
    bool valid = det > 1e-8f;
    float det_s = valid ? det : 1.0f;
    float ca =  syy / det_s;
    float cb = -sxy / det_s;
    float cc =  sxx / det_s;

    float mid = 0.5f * (sxx + syy);
    float lam = mid + sqrtf(fmaxf(mid * mid - det, 0.1f));
    int radii = valid ? (int)ceilf(3.0f * sqrtf(lam)) : 0;

    if (lane == 0) {
        if (out_size >= RENDER_SZ + NPTS)
            out[RENDER_SZ + g] = (float)radii;
        if (out_size >= RENDER_SZ + 2 * NPTS)
            out[RENDER_SZ + NPTS + g] = (radii > 0) ? 1.0f : 0.0f;
    }

    float x  = xy.x;
    float y  = xy.y;
    float op = opac[g];

    // Support cutoff: alpha >= 1/255  <=>  sigma <= Tcut.
    float Tcut = __logf(fmaxf(op, 1e-30f) * 255.0f);
    if (!valid || Tcut <= 0.0f) return;

    float cr  = sigmoidf_(fdc[3 * g + 0]);
    float cg  = sigmoidf_(fdc[3 * g + 1]);
    float cbl = sigmoidf_(fdc[3 * g + 2]);
    float fx0 = __expf(gf.x);
    float fy0 = __expf(gf.y);
    float fx1 = __expf(gf.z);
    float fy1 = __expf(gf.w);
    float w0  = sigmoidf_(gw.x);
    float w1  = sigmoidf_(gw.y);

    // Conservative bbox (superset of {alpha >= 1/255}) + 1px slop.
    float dxm = sqrtf(2.0f * Tcut * sxx) + 1.0f;
    float dym = sqrtf(2.0f * Tcut * syy) + 1.0f;
    int x0 = max(0, (int)floorf(x - dxm - 0.5f));
    int x1 = min(IMG_W - 1, (int)ceilf(x + dxm - 0.5f));
    int y0 = max(0, (int)floorf(y - dym - 0.5f));
    int y1 = min(IMG_H - 1, (int)ceilf(y + dym - 0.5f));
    int bw = x1 - x0 + 1;
    int bh = y1 - y0 + 1;
    if (bw <= 0 || bh <= 0) return;
    int npix = bw * bh;

    for (int t = lane; t < npix; t += 32) {
        int px = x0 + (t % bw);
        int py = y0 + (t / bw);
        float dx = ((float)px + 0.5f) - x;
        float dy = ((float)py + 0.5f) - y;
        float sigma = 0.5f * (ca * dx * dx + cc * dy * dy) + cb * (dx * dy);
        float alpha = fminf(op * __expf(-sigma), 0.999f);
        if (alpha < ALPHA_THRESH) continue;   // exact reference threshold
        float arg0 = fx0 * dx + fy0 * dy;
        float arg1 = fx1 * dx + fy1 * dy;
        float mod = 1.0f + w0 * __cosf(arg0) + w1 * __cosf(arg1);
        float wgt = alpha * mod;
        red_add_v4(&g_accum[py * IMG_W + px], wgt * cr, wgt * cg, wgt * cbl);
    }
}

// Each thread: 4 consecutive pixels. 4 independent float4 loads (MLP=4) from
// the interleaved accum; the 4 R components form one float4 store to the R
// plane (likewise G,B) -> fully coalesced planar output. Re-zero touched accum.
#define FIN_THREADS 256
#define FIN_BLOCKS  (HW / 4 / FIN_THREADS)    // 256

__global__ void __launch_bounds__(FIN_THREADS)
finish_kernel(float* __restrict__ out) {
    int t = blockIdx.x * FIN_THREADS + threadIdx.x;   // 0..65535
    int pix0 = t * 4;

    float4 a0 = g_accum[pix0 + 0];
    float4 a1 = g_accum[pix0 + 1];
    float4 a2 = g_accum[pix0 + 2];
    float4 a3 = g_accum[pix0 + 3];

    float4 r = make_float4(fminf(fmaxf(a0.x, 0.f), 1.f), fminf(fmaxf(a1.x, 0.f), 1.f),
                           fminf(fmaxf(a2.x, 0.f), 1.f), fminf(fmaxf(a3.x, 0.f), 1.f));
    float4 gg = make_float4(fminf(fmaxf(a0.y, 0.f), 1.f), fminf(fmaxf(a1.y, 0.f), 1.f),
                            fminf(fmaxf(a2.y, 0.f), 1.f), fminf(fmaxf(a3.y, 0.f), 1.f));
    float4 b = make_float4(fminf(fmaxf(a0.z, 0.f), 1.f), fminf(fmaxf(a1.z, 0.f), 1.f),
                           fminf(fmaxf(a2.z, 0.f), 1.f), fminf(fmaxf(a3.z, 0.f), 1.f));

    reinterpret_cast<float4*>(out)[t]          = r;
    reinterpret_cast<float4*>(out + HW)[t]     = gg;
    reinterpret_cast<float4*>(out + 2 * HW)[t] = b;

    const float4 z4 = make_float4(0.f, 0.f, 0.f, 0.f);
    if ((a0.x != 0.f) | (a0.y != 0.f) | (a0.z != 0.f)) g_accum[pix0 + 0] = z4;
    if ((a1.x != 0.f) | (a1.y != 0.f) | (a1.z != 0.f)) g_accum[pix0 + 1] = z4;
    if ((a2.x != 0.f) | (a2.y != 0.f) | (a2.z != 0.f)) g_accum[pix0 + 2] = z4;
    if ((a3.x != 0.f) | (a3.y != 0.f) | (a3.z != 0.f)) g_accum[pix0 + 3] = z4;
}

extern "C" void kernel_launch(void* const* d_in, const int* in_sizes, int n_in,
                              void* d_out, int out_size) {
    const float* xyz   = (const float*)d_in[0];
    const float* cov2d = (const float*)d_in[1];
    const float* fdc   = (const float*)d_in[2];
    const float* opac  = (const float*)d_in[3];
    const float* gfreq = (const float*)d_in[4];
    const float* gwt   = (const float*)d_in[5];
    float* out = (float*)d_out;

    splat_kernel<<<NPTS * 32 / 256, 256>>>(xyz, cov2d, fdc, opac, gfreq, gwt, out, out_size);
    finish_kernel<<<FIN_BLOCKS, FIN_THREADS>>>(out);
}

// round 8
// speedup vs baseline: 1.1857x; 1.1786x over previous
#include <cuda_runtime.h>
#include <math.h>

#define NPTS   2048
#define NGAB   2
#define IMG_H  512
#define IMG_W  512
#define HW     (IMG_H * IMG_W)
#define RENDER_SZ (3 * HW)
#define ALPHA_THRESH (1.0f / 255.0f)

// Planar accumulator. Zero at module load; finish re-zeroes touched entries
// after consuming, so every replay sees zeros.
__device__ float g_accum[RENDER_SZ];

__device__ __forceinline__ float sigmoidf_(float v) {
    return 1.0f / (1.0f + __expf(-v));
}

// One warp per Gaussian. Tight bbox, no per-iteration integer div.
__global__ void __launch_bounds__(128)
splat_kernel(const float* __restrict__ xyz,
             const float* __restrict__ cov2d,
             const float* __restrict__ fdc,
             const float* __restrict__ opac,
             const float* __restrict__ gfreq,
             const float* __restrict__ gwt,
             float* __restrict__ out, int out_size) {
    int g    = (blockIdx.x * blockDim.x + threadIdx.x) >> 5;
    int lane = threadIdx.x & 31;
    if (g >= NPTS) return;

    float2 xy = reinterpret_cast<const float2*>(xyz)[g];
    float4 gf = reinterpret_cast<const float4*>(gfreq)[g];
    float2 gw = reinterpret_cast<const float2*>(gwt)[g];

    float sxx = cov2d[3 * g + 0] + 0.5f;
    float sxy = cov2d[3 * g + 1];
    float syy = cov2d[3 * g + 2] + 0.5f;
    float det = sxx * syy - sxy * sxy;
    bool valid = det > 1e-8f;
    float det_s = valid ? det : 1.0f;
    float det_inv = __fdividef(1.0f, det_s);     // MUFU.RCP path
    float ca =  syy * det_inv;
    float cb = -sxy * det_inv;
    float cc =  sxx * det_inv;

    float mid = 0.5f * (sxx + syy);
    float lam = mid + sqrtf(fmaxf(mid * mid - det, 0.1f));  // IEEE sqrt: radii is ceil-sensitive
    int radii = valid ? (int)ceilf(3.0f * sqrtf(lam)) : 0;

    if (lane == 0) {
        if (out_size >= RENDER_SZ + NPTS)
            out[RENDER_SZ + g] = (float)radii;
        if (out_size >= RENDER_SZ + 2 * NPTS)
            out[RENDER_SZ + NPTS + g] = (radii > 0) ? 1.0f : 0.0f;
    }

    float x  = xy.x;
    float y  = xy.y;
    float op = opac[g];

    // Support cutoff: alpha >= 1/255  <=>  sigma <= Tcut.
    float Tcut = __logf(fmaxf(op, 1e-30f) * 255.0f);
    if (!valid || Tcut <= 0.0f) return;

    float cr  = sigmoidf_(fdc[3 * g + 0]);
    float cg  = sigmoidf_(fdc[3 * g + 1]);
    float cbl = sigmoidf_(fdc[3 * g + 2]);
    float fx0 = __expf(gf.x);
    float fy0 = __expf(gf.y);
    float fx1 = __expf(gf.z);
    float fy1 = __expf(gf.w);
    float w0  = sigmoidf_(gw.x);
    float w1  = sigmoidf_(gw.y);

    // Tight support extents: max |dx| on the sigma=Tcut level set is
    // sqrt(2*Tcut*sxx). 0.01px margin >> any fp error (sigma slack ~4e-2
    // vs reference fp noise ~1e-5).
    float ex2 = 2.0f * Tcut * sxx;
    float ey2 = 2.0f * Tcut * syy;
    float dxm = ex2 * rsqrtf(ex2) + 0.01f;
    float dym = ey2 * rsqrtf(ey2) + 0.01f;
    // Pixel center px+0.5 in [x-dxm, x+dxm]  =>  px in [ceil(x-dxm-0.5), floor(x+dxm-0.5)]
    int x0 = max(0, (int)ceilf(x - dxm - 0.5f));
    int x1 = min(IMG_W - 1, (int)floorf(x + dxm - 0.5f));
    int y0 = max(0, (int)ceilf(y - dym - 0.5f));
    int y1 = min(IMG_H - 1, (int)floorf(y + dym - 0.5f));
    int bw = x1 - x0 + 1;
    int bh = y1 - y0 + 1;
    if (bw <= 0 || bh <= 0) return;

    // Lane walk over the bbox without per-iteration div/mod:
    // start (row,col) from one int div; step by (+32) via carried counters.
    int row = lane / bw;          // one emulated div per warp-lane, outside loop
    int col = lane - row * bw;
    int s_row = 32 / bw;
    int s_col = 32 - s_row * bw;  // = 32 % bw, strictly < bw

    while (row < bh) {
        float dx = (float)(x0 + col) + 0.5f - x;
        float dy = (float)(y0 + row) + 0.5f - y;
        float sigma = 0.5f * (ca * dx * dx + cc * dy * dy) + cb * (dx * dy);
        float alpha = fminf(op * __expf(-sigma), 0.999f);
        if (alpha >= ALPHA_THRESH) {          // exact reference threshold
            float arg0 = fx0 * dx + fy0 * dy;
            float arg1 = fx1 * dx + fy1 * dy;
            float mod = 1.0f + w0 * __cosf(arg0) + w1 * __cosf(arg1);
            float wgt = alpha * mod;
            int pix = (y0 + row) * IMG_W + (x0 + col);
            atomicAdd(&g_accum[pix],          wgt * cr);
            atomicAdd(&g_accum[HW + pix],     wgt * cg);
            atomicAdd(&g_accum[2 * HW + pix], wgt * cbl);
        }
        col += s_col;
        row += s_row;
        if (col >= bw) { col -= bw; row += 1; }   // col was < 2*bw
    }
}

// Read accum -> clamp -> write d_out; re-zero accum where nonzero. ILP=4.
#define FIN_ILP 4
#define FIN_THREADS 256
#define FIN_BLOCKS (RENDER_SZ / 4 / FIN_ILP / FIN_THREADS)   // 192

__global__ void __launch_bounds__(FIN_THREADS)
finish_kernel(float* __restrict__ out) {
    int base = blockIdx.x * FIN_THREADS + threadIdx.x;
    const int stride = FIN_BLOCKS * FIN_THREADS;     // 49152
    float4* acc4 = reinterpret_cast<float4*>(g_accum);
    float4* out4 = reinterpret_cast<float4*>(out);

    float4 v[FIN_ILP];
    int idx[FIN_ILP];
    #pragma unroll
    for (int k = 0; k < FIN_ILP; k++) {
        idx[k] = base + k * stride;
        v[k] = acc4[idx[k]];
    }
    #pragma unroll
    for (int k = 0; k < FIN_ILP; k++) {
        float4 r = v[k];
        bool nz = (r.x != 0.0f) | (r.y != 0.0f) | (r.z != 0.0f) | (r.w != 0.0f);
        r.x = fminf(fmaxf(r.x, 0.0f), 1.0f);
        r.y = fminf(fmaxf(r.y, 0.0f), 1.0f);
        r.z = fminf(fmaxf(r.z, 0.0f), 1.0f);
        r.w = fminf(fmaxf(r.w, 0.0f), 1.0f);
        out4[idx[k]] = r;
        if (nz) acc4[idx[k]] = make_float4(0.0f, 0.0f, 0.0f, 0.0f);
    }
}

extern "C" void kernel_launch(void* const* d_in, const int* in_sizes, int n_in,
                              void* d_out, int out_size) {
    const float* xyz   = (const float*)d_in[0];
    const float* cov2d = (const float*)d_in[1];
    const float* fdc   = (const float*)d_in[2];
    const float* opac  = (const float*)d_in[3];
    const float* gfreq = (const float*)d_in[4];
    const float* gwt   = (const float*)d_in[5];
    float* out = (float*)d_out;

    splat_kernel<<<NPTS * 32 / 128, 128>>>(xyz, cov2d, fdc, opac, gfreq, gwt, out, out_size);
    finish_kernel<<<FIN_BLOCKS, FIN_THREADS>>>(out);
}

// round 9
// speedup vs baseline: 1.2206x; 1.0294x over previous
#include <cuda_runtime.h>
#include <math.h>

#define NPTS   2048
#define NGAB   2
#define IMG_H  512
#define IMG_W  512
#define HW     (IMG_H * IMG_W)
#define RENDER_SZ (3 * HW)
#define ALPHA_THRESH (1.0f / 255.0f)

#define LANES_PER_PT 64     // 2 warps per Gaussian

// Planar accumulator. Zero at module load; finish re-zeroes touched entries
// after consuming, so every replay sees zeros.
__device__ float g_accum[RENDER_SZ];

__device__ __forceinline__ float sigmoidf_(float v) {
    return 1.0f / (1.0f + __expf(-v));
}

// Two warps (64 lanes) per Gaussian. Tight bbox, carried row/col counters
// (no per-iteration div), sigma precheck to skip MUFU outside the ellipse.
__global__ void __launch_bounds__(128)
splat_kernel(const float* __restrict__ xyz,
             const float* __restrict__ cov2d,
             const float* __restrict__ fdc,
             const float* __restrict__ opac,
             const float* __restrict__ gfreq,
             const float* __restrict__ gwt,
             float* __restrict__ out, int out_size) {
    int gid = blockIdx.x * blockDim.x + threadIdx.x;
    int g   = gid >> 6;                 // Gaussian index
    int id  = gid & (LANES_PER_PT - 1); // 0..63 within the pair of warps
    if (g >= NPTS) return;

    float2 xy = reinterpret_cast<const float2*>(xyz)[g];
    float4 gf = reinterpret_cast<const float4*>(gfreq)[g];
    float2 gw = reinterpret_cast<const float2*>(gwt)[g];

    float sxx = cov2d[3 * g + 0] + 0.5f;
    float sxy = cov2d[3 * g + 1];
    float syy = cov2d[3 * g + 2] + 0.5f;
    float det = sxx * syy - sxy * sxy;
    bool valid = det > 1e-8f;
    float det_s = valid ? det : 1.0f;
    float det_inv = __fdividef(1.0f, det_s);
    float ca =  syy * det_inv;
    float cb = -sxy * det_inv;
    float cc =  sxx * det_inv;

    float mid = 0.5f * (sxx + syy);
    float lam = mid + sqrtf(fmaxf(mid * mid - det, 0.1f));  // IEEE sqrt: radii is ceil-sensitive
    int radii = valid ? (int)ceilf(3.0f * sqrtf(lam)) : 0;

    if (id == 0) {
        if (out_size >= RENDER_SZ + NPTS)
            out[RENDER_SZ + g] = (float)radii;
        if (out_size >= RENDER_SZ + 2 * NPTS)
            out[RENDER_SZ + NPTS + g] = (radii > 0) ? 1.0f : 0.0f;
    }

    float x  = xy.x;
    float y  = xy.y;
    float op = opac[g];

    // Support cutoff: alpha >= 1/255  <=>  sigma <= Tcut.
    float Tcut = __logf(fmaxf(op, 1e-30f) * 255.0f);
    if (!valid || Tcut <= 0.0f) return;

    float cr  = sigmoidf_(fdc[3 * g + 0]);
    float cg  = sigmoidf_(fdc[3 * g + 1]);
    float cbl = sigmoidf_(fdc[3 * g + 2]);
    float fx0 = __expf(gf.x);
    float fy0 = __expf(gf.y);
    float fx1 = __expf(gf.z);
    float fy1 = __expf(gf.w);
    float w0  = sigmoidf_(gw.x);
    float w1  = sigmoidf_(gw.y);

    // Tight support extents (0.01px margin >> fp noise).
    float ex2 = 2.0f * Tcut * sxx;
    float ey2 = 2.0f * Tcut * syy;
    float dxm = ex2 * rsqrtf(ex2) + 0.01f;
    float dym = ey2 * rsqrtf(ey2) + 0.01f;
    int x0 = max(0, (int)ceilf(x - dxm - 0.5f));
    int x1 = min(IMG_W - 1, (int)floorf(x + dxm - 0.5f));
    int y0 = max(0, (int)ceilf(y - dym - 0.5f));
    int y1 = min(IMG_H - 1, (int)floorf(y + dym - 0.5f));
    int bw = x1 - x0 + 1;
    int bh = y1 - y0 + 1;
    if (bw <= 0 || bh <= 0) return;

    // Walk bbox with stride 64, carried (row,col) — one int div total.
    int row = id / bw;
    int col = id - row * bw;
    int s_row = LANES_PER_PT / bw;
    int s_col = LANES_PER_PT - s_row * bw;   // < bw

    while (row < bh) {
        float dx = (float)(x0 + col) + 0.5f - x;
        float dy = (float)(y0 + row) + 0.5f - y;
        float sigma = 0.5f * (ca * dx * dx + cc * dy * dy) + cb * (dx * dy);
        // Outside the ellipse (with 1e-4 slack >> fp noise) alpha < 1/255 is
        // guaranteed; skip the MUFU block. Borderline takes the exact test.
        if (sigma <= Tcut + 1e-4f) {
            float alpha = fminf(op * __expf(-sigma), 0.999f);
            if (alpha >= ALPHA_THRESH) {      // exact reference threshold
                float arg0 = fx0 * dx + fy0 * dy;
                float arg1 = fx1 * dx + fy1 * dy;
                float mod = 1.0f + w0 * __cosf(arg0) + w1 * __cosf(arg1);
                float wgt = alpha * mod;
                int pix = (y0 + row) * IMG_W + (x0 + col);
                atomicAdd(&g_accum[pix],          wgt * cr);
                atomicAdd(&g_accum[HW + pix],     wgt * cg);
                atomicAdd(&g_accum[2 * HW + pix], wgt * cbl);
            }
        }
        col += s_col;
        row += s_row;
        if (col >= bw) { col -= bw; row += 1; }
    }
}

// Read accum -> clamp -> write d_out; re-zero accum where nonzero. ILP=4.
#define FIN_ILP 4
#define FIN_THREADS 256
#define FIN_BLOCKS (RENDER_SZ / 4 / FIN_ILP / FIN_THREADS)   // 192

__global__ void __launch_bounds__(FIN_THREADS)
finish_kernel(float* __restrict__ out) {
    int base = blockIdx.x * FIN_THREADS + threadIdx.x;
    const int stride = FIN_BLOCKS * FIN_THREADS;     // 49152
    float4* acc4 = reinterpret_cast<float4*>(g_accum);
    float4* out4 = reinterpret_cast<float4*>(out);

    float4 v[FIN_ILP];
    int idx[FIN_ILP];
    #pragma unroll
    for (int k = 0; k < FIN_ILP; k++) {
        idx[k] = base + k * stride;
        v[k] = acc4[idx[k]];
    }
    #pragma unroll
    for (int k = 0; k < FIN_ILP; k++) {
        float4 r = v[k];
        bool nz = (r.x != 0.0f) | (r.y != 0.0f) | (r.z != 0.0f) | (r.w != 0.0f);
        r.x = fminf(fmaxf(r.x, 0.0f), 1.0f);
        r.y = fminf(fmaxf(r.y, 0.0f), 1.0f);
        r.z = fminf(fmaxf(r.z, 0.0f), 1.0f);
        r.w = fminf(fmaxf(r.w, 0.0f), 1.0f);
        out4[idx[k]] = r;
        if (nz) acc4[idx[k]] = make_float4(0.0f, 0.0f, 0.0f, 0.0f);
    }
}

extern "C" void kernel_launch(void* const* d_in, const int* in_sizes, int n_in,
                              void* d_out, int out_size) {
    const float* xyz   = (const float*)d_in[0];
    const float* cov2d = (const float*)d_in[1];
    const float* fdc   = (const float*)d_in[2];
    const float* opac  = (const float*)d_in[3];
    const float* gfreq = (const float*)d_in[4];
    const float* gwt   = (const float*)d_in[5];
    float* out = (float*)d_out;

    splat_kernel<<<NPTS * LANES_PER_PT / 128, 128>>>(xyz, cov2d, fdc, opac, gfreq, gwt, out, out_size);
    finish_kernel<<<FIN_BLOCKS, FIN_THREADS>>>(out);
}